// round 8
// baseline (speedup 1.0000x reference)
#include <cuda_runtime.h>

// GAEChamferLoss: B=16, C=3, N=4096, mask in {0,1}.
// loss = mean_b( sum_{valid m} min_{valid n} ||x_n - y_m||^2 / cnt )
//      + mean_b( sum_{valid n} min_{valid m} ||x_n - y_m||^2 / cnt )

#define BB 16
#define NN 4096
#define BIGV 1e10f

#define INNER_SPLITS 4
#define THREADS 256
#define OUTER_PER_THREAD 4
#define OUTER_PER_BLOCK (THREADS * OUTER_PER_THREAD)            // 1024
#define OUTER_CHUNKS ((NN + OUTER_PER_BLOCK - 1) / OUTER_PER_BLOCK)  // 4
#define MAX_INNER ((NN + INNER_SPLITS - 1) / INNER_SPLITS)      // 1024

// Scratch (device globals — no allocations allowed)
__device__ float d_cx[BB * 3 * NN];   // compacted x, SoA per batch: [b][c][slot]
__device__ float d_cy[BB * 3 * NN];   // compacted y
__device__ int   d_cidx[BB * NN];     // original index per compacted slot
__device__ int   d_cnt[BB];           // valid count per batch
__device__ float d_mins[2 * BB * NN]; // [dir][b][orig_idx], init BIG
__device__ float d_sums[2 * BB];      // per (dir,b) mean of mins

__global__ void k_init() {
    int i = blockIdx.x * blockDim.x + threadIdx.x;
    if (i < 2 * BB * NN) d_mins[i] = BIGV;
    if (i < BB) d_cnt[i] = 0;
}

__global__ void k_compact(const float* __restrict__ x,
                          const float* __restrict__ y,
                          const int* __restrict__ mask) {
    int b = blockIdx.y;
    int i = blockIdx.x * blockDim.x + threadIdx.x;
    if (i >= NN) return;
    if (mask[b * NN + i]) {
        int slot = atomicAdd(&d_cnt[b], 1);
        #pragma unroll
        for (int c = 0; c < 3; c++) {
            d_cx[(b * 3 + c) * NN + slot] = x[(b * 3 + c) * NN + i];
            d_cy[(b * 3 + c) * NN + slot] = y[(b * 3 + c) * NN + i];
        }
        d_cidx[b * NN + slot] = i;
    }
}

// dir=0: outer = x (valid), inner = y (valid) -> mins2[b, orig_n]
// dir=1: outer = y (valid), inner = x (valid) -> mins1[b, orig_m]
__global__ __launch_bounds__(THREADS)
void k_main() {
    const int b = blockIdx.y;
    const int dir = blockIdx.z >> 2;                 // INNER_SPLITS = 4
    const int isplit = blockIdx.z & (INNER_SPLITS - 1);
    const int cnt = d_cnt[b];
    const int outer_base = blockIdx.x * OUTER_PER_BLOCK;
    if (outer_base >= cnt) return;

    const int chunk = (cnt + INNER_SPLITS - 1) / INNER_SPLITS;
    const int i0 = isplit * chunk;
    const int i1 = min(cnt, i0 + chunk);
    const int ilen = i1 - i0;
    if (ilen <= 0) return;

    const float* __restrict__ inner = dir ? d_cx : d_cy;
    const float* __restrict__ outer = dir ? d_cy : d_cx;

    __shared__ float s0[MAX_INNER];
    __shared__ float s1[MAX_INNER];
    __shared__ float s2[MAX_INNER];
    for (int j = threadIdx.x; j < ilen; j += THREADS) {
        s0[j] = inner[(b * 3 + 0) * NN + i0 + j];
        s1[j] = inner[(b * 3 + 1) * NN + i0 + j];
        s2[j] = inner[(b * 3 + 2) * NN + i0 + j];
    }
    __syncthreads();

    float ox[OUTER_PER_THREAD], oy[OUTER_PER_THREAD], oz[OUTER_PER_THREAD];
    float mn[OUTER_PER_THREAD];
    #pragma unroll
    for (int k = 0; k < OUTER_PER_THREAD; k++) {
        int o = outer_base + threadIdx.x + k * THREADS;
        int oc = (o < cnt) ? o : (cnt - 1);   // clamp; discarded at writeback
        ox[k] = outer[(b * 3 + 0) * NN + oc];
        oy[k] = outer[(b * 3 + 1) * NN + oc];
        oz[k] = outer[(b * 3 + 2) * NN + oc];
        mn[k] = BIGV;
    }

    #pragma unroll 2
    for (int j = 0; j < ilen; j++) {
        const float y0 = s0[j];
        const float y1 = s1[j];
        const float y2 = s2[j];
        #pragma unroll
        for (int k = 0; k < OUTER_PER_THREAD; k++) {
            float dx = ox[k] - y0;
            float dy = oy[k] - y1;
            float dz = oz[k] - y2;
            float d = fmaf(dz, dz, fmaf(dy, dy, dx * dx));  // >= 0 always
            mn[k] = fminf(mn[k], d);
        }
    }

    #pragma unroll
    for (int k = 0; k < OUTER_PER_THREAD; k++) {
        int o = outer_base + threadIdx.x + k * THREADS;
        if (o < cnt) {
            int orig = d_cidx[b * NN + o];
            // d >= 0 so int-min on the bit pattern == float-min
            atomicMin((int*)&d_mins[(dir * BB + b) * NN + orig],
                      __float_as_int(mn[k]));
        }
    }
}

__global__ void k_reduce(const int* __restrict__ mask) {
    const int b = blockIdx.x & (BB - 1);
    const int dir = blockIdx.x >> 4;
    __shared__ float red[256];
    float s = 0.f;
    for (int i = threadIdx.x; i < NN; i += 256)
        if (mask[b * NN + i]) s += d_mins[(dir * BB + b) * NN + i];
    red[threadIdx.x] = s;
    __syncthreads();
    for (int st = 128; st > 0; st >>= 1) {
        if (threadIdx.x < st) red[threadIdx.x] += red[threadIdx.x + st];
        __syncthreads();
    }
    if (threadIdx.x == 0)
        d_sums[blockIdx.x] = red[0] / (float)d_cnt[b];
}

__global__ void k_final(float* __restrict__ out) {
    if (threadIdx.x == 0) {
        float s = 0.f;
        #pragma unroll
        for (int i = 0; i < 2 * BB; i++) s += d_sums[i];
        out[0] = s / (float)BB;
    }
}

extern "C" void kernel_launch(void* const* d_in, const int* in_sizes, int n_in,
                              void* d_out, int out_size) {
    const float* x    = (const float*)d_in[0];
    const float* y    = (const float*)d_in[1];
    const int*   mask = (const int*)d_in[2];
    float* out = (float*)d_out;

    k_init<<<(2 * BB * NN + 255) / 256, 256>>>();

    dim3 gc((NN + 255) / 256, BB);
    k_compact<<<gc, 256>>>(x, y, mask);

    dim3 gm(OUTER_CHUNKS, BB, 2 * INNER_SPLITS);
    k_main<<<gm, THREADS>>>();

    k_reduce<<<2 * BB, 256>>>(mask);
    k_final<<<1, 32>>>(out);
}